// round 9
// baseline (speedup 1.0000x reference)
#include <cuda_runtime.h>
#include <cuda_fp16.h>
#include <math.h>
#include <stdint.h>

#define B_ 2
#define L_ 2048
#define H_ 8
#define D_ 64
#define F_ 5
#define KT 64
#define NT (L_/KT)
#define LUT_N 1024
#define DMAX 1.4143f
#define SMAX 12.0f

// prep outputs, layout [b*H+h][l][d]
__device__ __half  g_k16[B_*H_*L_*D_];   // f16(k)
__device__ __half  g_v16[B_*H_*L_*D_];   // f16(v)
__device__ uint8_t g_k8h[B_*H_*L_*D_];   // e5m2(k)
__device__ uint8_t g_k8l[B_*H_*L_*D_];   // e5m2(k - f16(k))
__device__ float2  g_lut2[H_][LUT_N+1];

// ---------------- smem layout (bytes) ----------------
#define STRB   144            // f16 tile row stride (64 halves used)
#define STR8   80             // fp8 tile row stride (64 bytes used)
#define OFF_K16 0
#define OFF_V16 9216
#define OFF_K8H 18432
#define OFF_K8L 23552
#define BUFSZ   28672
#define SM_LUT  0             // float2[1025] -> pad to 8320
#define SM_KS   8320          // float2[2][64] = 1024
#define SM_KV   9344          // two BUFSZ buffers
#define SM_Q16  SM_KV                 // transient (aliases buf0): 128*144 = 18432
#define SM_Q8H  (SM_KV + BUFSZ)       // transient (buf1): 128*80 = 10240
#define SM_Q8L  (SM_KV + BUFSZ + 10240)
#define SMEM_TOTAL (SM_KV + 2*BUFSZ)  // 66688 -> 2 CTAs/SM

__device__ __forceinline__ uint32_t s2u(const void* p) {
    uint32_t a;
    asm("{ .reg .u64 t; cvta.to.shared.u64 t, %1; cvt.u32.u64 %0, t; }"
        : "=r"(a) : "l"(p));
    return a;
}

#define CP16(dst, src) \
    asm volatile("cp.async.cg.shared.global [%0], [%1], 16;" :: "r"(dst), "l"(src))
#define CPCOMMIT() asm volatile("cp.async.commit_group;" ::: "memory")
#define CPWAIT(n)  asm volatile("cp.async.wait_group %0;" :: "n"(n) : "memory")

#define LDSM4(R, addr) \
    asm volatile("ldmatrix.sync.aligned.m8n8.x4.shared.b16 {%0,%1,%2,%3}, [%4];" \
        : "=r"((R)[0]), "=r"((R)[1]), "=r"((R)[2]), "=r"((R)[3]) : "r"(addr))
#define LDSM4T(R, addr) \
    asm volatile("ldmatrix.sync.aligned.m8n8.x4.trans.shared.b16 {%0,%1,%2,%3}, [%4];" \
        : "=r"((R)[0]), "=r"((R)[1]), "=r"((R)[2]), "=r"((R)[3]) : "r"(addr))

#define MMAF16(C, A, b0, b1) \
    asm volatile("mma.sync.aligned.m16n8k16.row.col.f32.f16.f16.f32 " \
        "{%0,%1,%2,%3}, {%4,%5,%6,%7}, {%8,%9}, {%0,%1,%2,%3};" \
        : "+f"((C)[0]), "+f"((C)[1]), "+f"((C)[2]), "+f"((C)[3]) \
        : "r"((A)[0]), "r"((A)[1]), "r"((A)[2]), "r"((A)[3]), "r"(b0), "r"(b1))

#define MMAF8(C, A, b0, b1) \
    asm volatile("mma.sync.aligned.m16n8k32.row.col.f32.e5m2.e5m2.f32 " \
        "{%0,%1,%2,%3}, {%4,%5,%6,%7}, {%8,%9}, {%0,%1,%2,%3};" \
        : "+f"((C)[0]), "+f"((C)[1]), "+f"((C)[2]), "+f"((C)[3]) \
        : "r"((A)[0]), "r"((A)[1]), "r"((A)[2]), "r"((A)[3]), "r"(b0), "r"(b1))

// pack two f32 -> f16x2 (lo = x0) and f16-residual pair
__device__ __forceinline__ void split2h(float x0, float x1, uint32_t& h, uint32_t& l) {
    __half2 hh = __floats2half2_rn(x0, x1);
    float2 bk = __half22float2(hh);
    __half2 ll = __floats2half2_rn(x0 - bk.x, x1 - bk.y);
    h = *(uint32_t*)&hh;
    l = *(uint32_t*)&ll;
}
// pack 4 f32 -> 4 e5m2 bytes ascending (cvt e5m2x2 writes a .b16 register!)
__device__ __forceinline__ uint32_t pack_e5m2_4(float x0, float x1, float x2, float x3) {
    uint16_t c01, c23;
    asm("cvt.rn.satfinite.e5m2x2.f32 %0, %1, %2;" : "=h"(c01) : "f"(x1), "f"(x0));
    asm("cvt.rn.satfinite.e5m2x2.f32 %0, %1, %2;" : "=h"(c23) : "f"(x3), "f"(x2));
    return (uint32_t)c01 | ((uint32_t)c23 << 16);
}

// ---------------- prep: K -> f16 + e5m2 hi/lo, V -> f16 ----------------
__global__ void prep_kernel(const float4* __restrict__ ks, const float4* __restrict__ vs) {
    int i = blockIdx.x * blockDim.x + threadIdx.x;
    if (i >= B_ * H_ * L_ * D_ / 4) return;
    int d4 = i & 15, h = (i >> 4) & 7, l = (i >> 7) & 2047, b = i >> 18;
    int dst4 = (((b * H_ + h) * L_ + l) * D_) / 4 + d4;
    float4 k = ks[i];
    __half2 h01 = __floats2half2_rn(k.x, k.y);
    __half2 h23 = __floats2half2_rn(k.z, k.w);
    ((__half2*)g_k16)[dst4 * 2]     = h01;
    ((__half2*)g_k16)[dst4 * 2 + 1] = h23;
    float2 b01 = __half22float2(h01);
    float2 b23 = __half22float2(h23);
    ((uint32_t*)g_k8h)[dst4] = pack_e5m2_4(k.x, k.y, k.z, k.w);
    ((uint32_t*)g_k8l)[dst4] = pack_e5m2_4(k.x - b01.x, k.y - b01.y,
                                           k.z - b23.x, k.w - b23.y);
    float4 v = vs[i];
    ((__half2*)g_v16)[dst4 * 2]     = __floats2half2_rn(v.x, v.y);
    ((__half2*)g_v16)[dst4 * 2 + 1] = __floats2half2_rn(v.z, v.w);
}

__global__ void lut_kernel(const float* __restrict__ a, const float* __restrict__ b,
                           const float* __restrict__ c) {
    int h = blockIdx.y;
    int i = blockIdx.x * blockDim.x + threadIdx.x;
    if (i > LUT_N) return;
    float g[2];
#pragma unroll
    for (int t = 0; t < 2; t++) {
        float d = (float)(i + t) * (DMAX / (float)LUT_N);
        float s = 0.f;
#pragma unroll
        for (int f = 0; f < F_; f++) {
            float dt = d - c[h * F_ + f];
            s += a[h * F_ + f] * expf(-fabsf(b[h * F_ + f]) * dt * dt);
        }
        g[t] = s;
    }
    g_lut2[h][i] = make_float2(g[0], g[1]);
}

// ---------------- main attention kernel ----------------
__global__ __launch_bounds__(256, 2)
void attn_kernel(const float* __restrict__ qs, const float* __restrict__ qs_s,
                 const float* __restrict__ ks_s, float* __restrict__ out) {
    extern __shared__ char smem[];
    const uint32_t sb = s2u(smem);
    const int tid = threadIdx.x;
    const int w = tid >> 5, lane = tid & 31;
    const int gid = lane >> 2, tig = lane & 3;
    const int b = blockIdx.z, h = blockIdx.y;
    const int q0 = blockIdx.x * 128;
    const int bh = b * H_ + h;

    const char* gk16 = (const char*)g_k16 + (size_t)bh * L_ * D_ * 2;
    const char* gv16 = (const char*)g_v16 + (size_t)bh * L_ * D_ * 2;
    const char* gk8h = (const char*)g_k8h + (size_t)bh * L_ * D_;
    const char* gk8l = (const char*)g_k8l + (size_t)bh * L_ * D_;

#define ISSUE_TILE(t, bsel) do {                                               \
    int _k0 = (t) * KT;                                                        \
    uint32_t _bb = sb + SM_KV + (bsel) * BUFSZ;                                \
    int _r16 = tid >> 3, _s16 = tid & 7;                                       \
    _Pragma("unroll")                                                          \
    for (int _i = 0; _i < 2; _i++) {                                           \
        int rr = _r16 + _i * 32;                                               \
        size_t so = (size_t)(_k0 + rr) * 128 + _s16 * 16;                      \
        CP16(_bb + OFF_K16 + rr * STRB + _s16 * 16, gk16 + so);                \
        CP16(_bb + OFF_V16 + rr * STRB + _s16 * 16, gv16 + so);                \
    }                                                                          \
    {                                                                          \
        int r8 = tid >> 2, s8 = tid & 3;                                       \
        size_t so8 = (size_t)(_k0 + r8) * 64 + s8 * 16;                        \
        CP16(_bb + OFF_K8H + r8 * STR8 + s8 * 16, gk8h + so8);                 \
        CP16(_bb + OFF_K8L + r8 * STR8 + s8 * 16, gk8l + so8);                 \
    }                                                                          \
    if (tid < 64)                                                              \
        *(float2*)(smem + SM_KS + (bsel) * 512 + tid * 8) =                    \
            ((const float2*)ks_s)[b * L_ + _k0 + tid];                         \
} while (0)

    // ---- prologue: LUT + Q staging (f16 + e5m2 hi/lo) ----
    float2* sLut = (float2*)(smem + SM_LUT);
    for (int i = tid; i <= LUT_N; i += 256) sLut[i] = g_lut2[h][i];
    {
        int r = tid >> 1, dq = (tid & 1) * 32;
        const float4* gq = (const float4*)(qs + (((size_t)b * L_ + q0 + r) * H_ + h) * D_ + dq);
#pragma unroll
        for (int i = 0; i < 8; i++) {
            float4 v = gq[i];
            v.x *= 0.125f; v.y *= 0.125f; v.z *= 0.125f; v.w *= 0.125f;
            __half2 h01 = __floats2half2_rn(v.x, v.y);
            __half2 h23 = __floats2half2_rn(v.z, v.w);
            *(uint2*)(smem + SM_Q16 + r * STRB + dq * 2 + i * 8) =
                make_uint2(*(uint32_t*)&h01, *(uint32_t*)&h23);
            float2 b01 = __half22float2(h01);
            float2 b23 = __half22float2(h23);
            *(uint32_t*)(smem + SM_Q8H + r * STR8 + dq + i * 4) =
                pack_e5m2_4(v.x, v.y, v.z, v.w);
            *(uint32_t*)(smem + SM_Q8L + r * STR8 + dq + i * 4) =
                pack_e5m2_4(v.x - b01.x, v.y - b01.y, v.z - b23.x, v.w - b23.y);
        }
    }
    __syncthreads();

    // Q fragments (register-resident)
    uint32_t qh16[4][4], q8h[2][4], q8l[2][4];
    {
        uint32_t qa16 = sb + SM_Q16 + (16 * w + (lane & 7) + ((lane >> 3) & 1) * 8) * STRB
                      + ((lane >> 4) & 1) * 16;
#pragma unroll
        for (int kt = 0; kt < 4; kt++) LDSM4(qh16[kt], qa16 + kt * 32);
        uint32_t qa8h = sb + SM_Q8H + (16 * w + (lane & 7) + ((lane >> 3) & 1) * 8) * STR8
                      + ((lane >> 4) & 1) * 16;
        LDSM4(q8h[0], qa8h);
        LDSM4(q8h[1], qa8h + 32);
        uint32_t qa8l = qa8h + (SM_Q8L - SM_Q8H);
        LDSM4(q8l[0], qa8l);
        LDSM4(q8l[1], qa8l + 32);
    }
    __syncthreads();     // Q staging regions now free -> become KV buffers

    ISSUE_TILE(0, 0);
    CPCOMMIT();

    const float2 qsA = ((const float2*)qs_s)[b * L_ + q0 + 16 * w + gid];
    const float2 qsB = ((const float2*)qs_s)[b * L_ + q0 + 16 * w + gid + 8];
    const float dscale = (float)LUT_N / DMAX;

    const uint32_t klane16 = ((lane & 7) + ((lane >> 4) & 1) * 8) * STRB + ((lane >> 3) & 1) * 16;
    const uint32_t klane8  = (lane & 7) * STR8 + ((lane >> 3) & 3) * 16;
    const uint32_t vlane   = ((lane & 7) + ((lane >> 3) & 1) * 8) * STRB + ((lane >> 4) & 1) * 16;

    float O[8][4];
#pragma unroll
    for (int n = 0; n < 8; n++)
#pragma unroll
        for (int c = 0; c < 4; c++) O[n][c] = 0.f;
    float lpA = 0.f, lpB = 0.f;

    for (int t = 0; t < NT; t++) {
        const int buf = t & 1;
        if (t + 1 < NT) { ISSUE_TILE(t + 1, buf ^ 1); CPCOMMIT(); }
        if (t + 1 < NT) { CPWAIT(1); } else { CPWAIT(0); }
        __syncthreads();

        const uint32_t bb = sb + SM_KV + buf * BUFSZ;
        const char* ksb = smem + SM_KS + buf * 512;

#pragma unroll
        for (int half = 0; half < 2; half++) {
            // ---- QK for keys 32*half .. +31 : S[4][4] ----
            float S[4][4];
#pragma unroll
            for (int j = 0; j < 4; j++)
#pragma unroll
                for (int c = 0; c < 4; c++) S[j][c] = 0.f;

            // fp16 main pass
            const uint32_t kb16 = bb + OFF_K16 + (32 * half) * STRB + klane16;
#pragma unroll
            for (int jp = 0; jp < 2; jp++) {
#pragma unroll
                for (int kt = 0; kt < 4; kt++) {
                    uint32_t khf[4];
                    LDSM4(khf, kb16 + jp * (16 * STRB) + kt * 32);
                    MMAF16(S[2 * jp],     qh16[kt], khf[0], khf[1]);
                    MMAF16(S[2 * jp + 1], qh16[kt], khf[2], khf[3]);
                }
            }
            // fp8 correction passes: Qlo*Khi + Qhi*Klo
            const uint32_t kb8h = bb + OFF_K8H + (32 * half) * STR8 + klane8;
            const uint32_t kb8l = bb + OFF_K8L + (32 * half) * STR8 + klane8;
#pragma unroll
            for (int j = 0; j < 4; j++) {
                uint32_t R[4];
                LDSM4(R, kb8h + j * (8 * STR8));
                MMAF8(S[j], q8l[0], R[0], R[1]);
                MMAF8(S[j], q8l[1], R[2], R[3]);
                uint32_t Rl[4];
                LDSM4(Rl, kb8l + j * (8 * STR8));
                MMAF8(S[j], q8h[0], Rl[0], Rl[1]);
                MMAF8(S[j], q8h[1], Rl[2], Rl[3]);
            }

            // ---- epilogue: bias + fixed-max exp + pack P (f16 hi/lo) ----
            uint32_t PH[2][4], PL[2][4];
#pragma unroll
            for (int j = 0; j < 4; j++) {
                int col = 32 * half + 8 * j + 2 * tig;
                float2 k0 = *(const float2*)(ksb + col * 8);
                float2 k1 = *(const float2*)(ksb + col * 8 + 8);
                float p[4];
#pragma unroll
                for (int e = 0; e < 4; e++) {
                    float2 qq = (e < 2) ? qsA : qsB;
                    float2 kk = (e & 1) ? k1 : k0;
                    float dx = qq.x - kk.x, dy = qq.y - kk.y;
                    float dd;
                    asm("sqrt.approx.f32 %0, %1;" : "=f"(dd) : "f"(fmaf(dx, dx, dy * dy)));
                    float tt = fminf(dd * dscale, (float)LUT_N - 0.001f);
                    int ii = (int)tt;
                    float fr = tt - (float)ii;
                    float2 g = sLut[ii];
                    float s = S[j][e] + g.x + fr * (g.y - g.x);
                    p[e] = __expf(s - SMAX);
                }
                lpA += p[0] + p[1];
                lpB += p[2] + p[3];
                int m = j >> 1, slot = (j & 1) * 2;
                split2h(p[0], p[1], PH[m][slot],     PL[m][slot]);
                split2h(p[2], p[3], PH[m][slot + 1], PL[m][slot + 1]);
            }

            // ---- PV (2-pass): O += (Phi + Plo) @ Vhi ----
#pragma unroll
            for (int m = 0; m < 2; m++) {
                const uint32_t vb = bb + OFF_V16 + (2 * half + m) * (16 * STRB) + vlane;
#pragma unroll
                for (int np = 0; np < 4; np++) {
                    uint32_t vhf[4];
                    LDSM4T(vhf, vb + np * 32);
                    MMAF16(O[2 * np],     PH[m], vhf[0], vhf[1]);
                    MMAF16(O[2 * np],     PL[m], vhf[0], vhf[1]);
                    MMAF16(O[2 * np + 1], PH[m], vhf[2], vhf[3]);
                    MMAF16(O[2 * np + 1], PL[m], vhf[2], vhf[3]);
                }
            }
        }
        __syncthreads();
    }

    // ---- finalize ----
    lpA += __shfl_xor_sync(0xffffffffu, lpA, 1);
    lpA += __shfl_xor_sync(0xffffffffu, lpA, 2);
    lpB += __shfl_xor_sync(0xffffffffu, lpB, 1);
    lpB += __shfl_xor_sync(0xffffffffu, lpB, 2);
    float invA = 1.0f / lpA, invB = 1.0f / lpB;

    int rA = q0 + 16 * w + gid;
    float* outA = &out[(((size_t)b * L_ + rA) * H_ + h) * D_ + 2 * tig];
    float* outB = &out[(((size_t)b * L_ + rA + 8) * H_ + h) * D_ + 2 * tig];
#pragma unroll
    for (int n = 0; n < 8; n++) {
        *(float2*)(outA + 8 * n) = make_float2(O[n][0] * invA, O[n][1] * invA);
        *(float2*)(outB + 8 * n) = make_float2(O[n][2] * invB, O[n][3] * invB);
    }
}

extern "C" void kernel_launch(void* const* d_in, const int* in_sizes, int n_in,
                              void* d_out, int out_size) {
    const float* qs   = (const float*)d_in[0];
    const float* ks   = (const float*)d_in[1];
    const float* vs   = (const float*)d_in[2];
    const float* qs_s = (const float*)d_in[3];
    const float* ks_s = (const float*)d_in[4];
    const float* a    = (const float*)d_in[5];
    const float* b    = (const float*)d_in[6];
    const float* c    = (const float*)d_in[7];
    float* out = (float*)d_out;

    prep_kernel<<<(B_ * H_ * L_ * D_ / 4 + 255) / 256, 256>>>(
        (const float4*)ks, (const float4*)vs);
    lut_kernel<<<dim3((LUT_N + 128) / 128, H_), 128>>>(a, b, c);

    cudaFuncSetAttribute(attn_kernel,
                         cudaFuncAttributeMaxDynamicSharedMemorySize, SMEM_TOTAL);
    attn_kernel<<<dim3(L_ / 128, H_, B_), 256, SMEM_TOTAL>>>(qs, qs_s, ks_s, out);
}

// round 10
// speedup vs baseline: 1.7505x; 1.7505x over previous
#include <cuda_runtime.h>
#include <cuda_fp16.h>
#include <math.h>
#include <stdint.h>

#define B_ 2
#define L_ 2048
#define H_ 8
#define D_ 64
#define F_ 5
#define KT 64
#define NT (L_/KT)
#define LUT_N 1024
#define DMAX 1.4143f
#define SMAX 12.0f
#define LOG2E 1.4426950408889634f

// prep outputs, layout [b*H+h][l][d]
__device__ __half  g_k16[B_*H_*L_*D_];   // f16(k)
__device__ __half  g_v16[B_*H_*L_*D_];   // f16(v)
__device__ float2  g_lut2[H_][LUT_N+1];  // (A, D): A=(g-12)*log2e, D=dg*log2e

// ---------------- smem layout (bytes) ----------------
#define STRB    144           // f16 tile row stride (64 halves used)
#define OFF_K16 0
#define OFF_V16 9216
#define BUFSZ   18432
#define SM_LUT  0             // float2[1025] -> pad to 8320
#define SM_KS   8320          // float2[2][64] = 1024
#define SM_KV   9344          // two BUFSZ buffers
#define SM_Q16  SM_KV         // transient Q staging (aliases buf0): 128*144
#define SMEM_TOTAL (SM_KV + 2*BUFSZ)   // 46208 -> 2 CTAs/SM

__device__ __forceinline__ uint32_t s2u(const void* p) {
    uint32_t a;
    asm("{ .reg .u64 t; cvta.to.shared.u64 t, %1; cvt.u32.u64 %0, t; }"
        : "=r"(a) : "l"(p));
    return a;
}

#define CP16(dst, src) \
    asm volatile("cp.async.cg.shared.global [%0], [%1], 16;" :: "r"(dst), "l"(src))
#define CPCOMMIT() asm volatile("cp.async.commit_group;" ::: "memory")
#define CPWAIT(n)  asm volatile("cp.async.wait_group %0;" :: "n"(n) : "memory")

#define LDSM4(R, addr) \
    asm volatile("ldmatrix.sync.aligned.m8n8.x4.shared.b16 {%0,%1,%2,%3}, [%4];" \
        : "=r"((R)[0]), "=r"((R)[1]), "=r"((R)[2]), "=r"((R)[3]) : "r"(addr))
#define LDSM4T(R, addr) \
    asm volatile("ldmatrix.sync.aligned.m8n8.x4.trans.shared.b16 {%0,%1,%2,%3}, [%4];" \
        : "=r"((R)[0]), "=r"((R)[1]), "=r"((R)[2]), "=r"((R)[3]) : "r"(addr))

#define MMAF16(C, A, b0, b1) \
    asm volatile("mma.sync.aligned.m16n8k16.row.col.f32.f16.f16.f32 " \
        "{%0,%1,%2,%3}, {%4,%5,%6,%7}, {%8,%9}, {%0,%1,%2,%3};" \
        : "+f"((C)[0]), "+f"((C)[1]), "+f"((C)[2]), "+f"((C)[3]) \
        : "r"((A)[0]), "r"((A)[1]), "r"((A)[2]), "r"((A)[3]), "r"(b0), "r"(b1))

__device__ __forceinline__ uint32_t packh2(float x0, float x1) {
    __half2 hh = __floats2half2_rn(x0, x1);
    return *(uint32_t*)&hh;
}
__device__ __forceinline__ float ex2(float x) {
    float r;
    asm("ex2.approx.f32 %0, %1;" : "=f"(r) : "f"(x));
    return r;
}

// ---------------- prep: K,V -> f16 ----------------
__global__ void prep_kernel(const float4* __restrict__ ks, const float4* __restrict__ vs) {
    int i = blockIdx.x * blockDim.x + threadIdx.x;
    if (i >= B_ * H_ * L_ * D_ / 4) return;
    int d4 = i & 15, h = (i >> 4) & 7, l = (i >> 7) & 2047, b = i >> 18;
    int dst4 = (((b * H_ + h) * L_ + l) * D_) / 4 + d4;
    float4 k = ks[i];
    ((__half2*)g_k16)[dst4 * 2]     = __floats2half2_rn(k.x, k.y);
    ((__half2*)g_k16)[dst4 * 2 + 1] = __floats2half2_rn(k.z, k.w);
    float4 v = vs[i];
    ((__half2*)g_v16)[dst4 * 2]     = __floats2half2_rn(v.x, v.y);
    ((__half2*)g_v16)[dst4 * 2 + 1] = __floats2half2_rn(v.z, v.w);
}

__global__ void lut_kernel(const float* __restrict__ a, const float* __restrict__ b,
                           const float* __restrict__ c) {
    int h = blockIdx.y;
    int i = blockIdx.x * blockDim.x + threadIdx.x;
    if (i > LUT_N) return;
    float g[2];
#pragma unroll
    for (int t = 0; t < 2; t++) {
        float d = (float)(i + t) * (DMAX / (float)LUT_N);
        float s = 0.f;
#pragma unroll
        for (int f = 0; f < F_; f++) {
            float dt = d - c[h * F_ + f];
            s += a[h * F_ + f] * expf(-fabsf(b[h * F_ + f]) * dt * dt);
        }
        g[t] = s;
    }
    // store (A, D) pre-scaled so exp(s-SMAX) == ex2(S + A + fr*D)
    g_lut2[h][i] = make_float2((g[0] - SMAX) * LOG2E, (g[1] - g[0]) * LOG2E);
}

// ---------------- main attention kernel ----------------
__global__ __launch_bounds__(256, 2)
void attn_kernel(const float* __restrict__ qs, const float* __restrict__ qs_s,
                 const float* __restrict__ ks_s, float* __restrict__ out) {
    extern __shared__ char smem[];
    const uint32_t sb = s2u(smem);
    const int tid = threadIdx.x;
    const int w = tid >> 5, lane = tid & 31;
    const int gid = lane >> 2, tig = lane & 3;
    const int b = blockIdx.z, h = blockIdx.y;
    const int q0 = blockIdx.x * 128;
    const int bh = b * H_ + h;

    const char* gk16 = (const char*)g_k16 + (size_t)bh * L_ * D_ * 2;
    const char* gv16 = (const char*)g_v16 + (size_t)bh * L_ * D_ * 2;

#define ISSUE_TILE(t, bsel) do {                                               \
    int _k0 = (t) * KT;                                                        \
    uint32_t _bb = sb + SM_KV + (bsel) * BUFSZ;                                \
    int _r16 = tid >> 3, _s16 = tid & 7;                                       \
    _Pragma("unroll")                                                          \
    for (int _i = 0; _i < 2; _i++) {                                           \
        int rr = _r16 + _i * 32;                                               \
        size_t so = (size_t)(_k0 + rr) * 128 + _s16 * 16;                      \
        CP16(_bb + OFF_K16 + rr * STRB + _s16 * 16, gk16 + so);                \
        CP16(_bb + OFF_V16 + rr * STRB + _s16 * 16, gv16 + so);                \
    }                                                                          \
    if (tid < 64)                                                              \
        *(float2*)(smem + SM_KS + (bsel) * 512 + tid * 8) =                    \
            ((const float2*)ks_s)[b * L_ + _k0 + tid];                         \
} while (0)

    // ---- prologue: LUT + Q staging (f16, scaled by log2e/8) ----
    float2* sLut = (float2*)(smem + SM_LUT);
    for (int i = tid; i <= LUT_N; i += 256) sLut[i] = g_lut2[h][i];
    {
        const float qscale = 0.125f * LOG2E;
        int r = tid >> 1, dq = (tid & 1) * 32;
        const float4* gq = (const float4*)(qs + (((size_t)b * L_ + q0 + r) * H_ + h) * D_ + dq);
#pragma unroll
        for (int i = 0; i < 8; i++) {
            float4 v = gq[i];
            *(uint2*)(smem + SM_Q16 + r * STRB + dq * 2 + i * 8) =
                make_uint2(packh2(v.x * qscale, v.y * qscale),
                           packh2(v.z * qscale, v.w * qscale));
        }
    }
    __syncthreads();

    // Q fragments (register-resident)
    uint32_t qh16[4][4];
    {
        uint32_t qa16 = sb + SM_Q16 + (16 * w + (lane & 7) + ((lane >> 3) & 1) * 8) * STRB
                      + ((lane >> 4) & 1) * 16;
#pragma unroll
        for (int kt = 0; kt < 4; kt++) LDSM4(qh16[kt], qa16 + kt * 32);
    }
    __syncthreads();     // Q staging region now free -> becomes buf0

    ISSUE_TILE(0, 0);
    CPCOMMIT();

    const float2 qsA = ((const float2*)qs_s)[b * L_ + q0 + 16 * w + gid];
    const float2 qsB = ((const float2*)qs_s)[b * L_ + q0 + 16 * w + gid + 8];
    const float dscale = (float)LUT_N / DMAX;

    const uint32_t klane16 = ((lane & 7) + ((lane >> 4) & 1) * 8) * STRB + ((lane >> 3) & 1) * 16;
    const uint32_t vlane   = ((lane & 7) + ((lane >> 3) & 1) * 8) * STRB + ((lane >> 4) & 1) * 16;

    float O[8][4];
#pragma unroll
    for (int n = 0; n < 8; n++)
#pragma unroll
        for (int c = 0; c < 4; c++) O[n][c] = 0.f;
    float lpA = 0.f, lpB = 0.f;

    for (int t = 0; t < NT; t++) {
        const int buf = t & 1;
        if (t + 1 < NT) { ISSUE_TILE(t + 1, buf ^ 1); CPCOMMIT(); }
        if (t + 1 < NT) { CPWAIT(1); } else { CPWAIT(0); }
        __syncthreads();

        const uint32_t bb = sb + SM_KV + buf * BUFSZ;
        const char* ksb = smem + SM_KS + buf * 512;

#pragma unroll
        for (int half = 0; half < 2; half++) {
            // ---- QK for keys 32*half .. +31 : S[4][4] (single f16 pass) ----
            float S[4][4];
#pragma unroll
            for (int j = 0; j < 4; j++)
#pragma unroll
                for (int c = 0; c < 4; c++) S[j][c] = 0.f;

            const uint32_t kb16 = bb + OFF_K16 + (32 * half) * STRB + klane16;
#pragma unroll
            for (int jp = 0; jp < 2; jp++) {
#pragma unroll
                for (int kt = 0; kt < 4; kt++) {
                    uint32_t khf[4];
                    LDSM4(khf, kb16 + jp * (16 * STRB) + kt * 32);
                    MMAF16(S[2 * jp],     qh16[kt], khf[0], khf[1]);
                    MMAF16(S[2 * jp + 1], qh16[kt], khf[2], khf[3]);
                }
            }

            // ---- epilogue: bias LUT + ex2 + rowsum + pack P (f16) ----
            uint32_t PH[2][4];
#pragma unroll
            for (int j = 0; j < 4; j++) {
                int col = 32 * half + 8 * j + 2 * tig;
                float2 k0 = *(const float2*)(ksb + col * 8);
                float2 k1 = *(const float2*)(ksb + col * 8 + 8);
                float p[4];
#pragma unroll
                for (int e = 0; e < 4; e++) {
                    float2 qq = (e < 2) ? qsA : qsB;
                    float2 kk = (e & 1) ? k1 : k0;
                    float dx = qq.x - kk.x, dy = qq.y - kk.y;
                    float dd;
                    asm("sqrt.approx.f32 %0, %1;" : "=f"(dd) : "f"(fmaf(dx, dx, dy * dy)));
                    float tt = fminf(dd * dscale, (float)LUT_N - 0.001f);
                    int ii = (int)tt;
                    float fr = tt - (float)ii;
                    float2 g = sLut[ii];
                    p[e] = ex2(S[j][e] + fmaf(fr, g.y, g.x));
                }
                lpA += p[0] + p[1];
                lpB += p[2] + p[3];
                int m = j >> 1, slot = (j & 1) * 2;
                PH[m][slot]     = packh2(p[0], p[1]);
                PH[m][slot + 1] = packh2(p[2], p[3]);
            }

            // ---- PV (single pass): O += P @ V ----
#pragma unroll
            for (int m = 0; m < 2; m++) {
                const uint32_t vb = bb + OFF_V16 + (2 * half + m) * (16 * STRB) + vlane;
#pragma unroll
                for (int np = 0; np < 4; np++) {
                    uint32_t vhf[4];
                    LDSM4T(vhf, vb + np * 32);
                    MMAF16(O[2 * np],     PH[m], vhf[0], vhf[1]);
                    MMAF16(O[2 * np + 1], PH[m], vhf[2], vhf[3]);
                }
            }
        }
        __syncthreads();
    }

    // ---- finalize ----
    lpA += __shfl_xor_sync(0xffffffffu, lpA, 1);
    lpA += __shfl_xor_sync(0xffffffffu, lpA, 2);
    lpB += __shfl_xor_sync(0xffffffffu, lpB, 1);
    lpB += __shfl_xor_sync(0xffffffffu, lpB, 2);
    float invA = 1.0f / lpA, invB = 1.0f / lpB;

    int rA = q0 + 16 * w + gid;
    float* outA = &out[(((size_t)b * L_ + rA) * H_ + h) * D_ + 2 * tig];
    float* outB = &out[(((size_t)b * L_ + rA + 8) * H_ + h) * D_ + 2 * tig];
#pragma unroll
    for (int n = 0; n < 8; n++) {
        *(float2*)(outA + 8 * n) = make_float2(O[n][0] * invA, O[n][1] * invA);
        *(float2*)(outB + 8 * n) = make_float2(O[n][2] * invB, O[n][3] * invB);
    }
}

extern "C" void kernel_launch(void* const* d_in, const int* in_sizes, int n_in,
                              void* d_out, int out_size) {
    const float* qs   = (const float*)d_in[0];
    const float* ks   = (const float*)d_in[1];
    const float* vs   = (const float*)d_in[2];
    const float* qs_s = (const float*)d_in[3];
    const float* ks_s = (const float*)d_in[4];
    const float* a    = (const float*)d_in[5];
    const float* b    = (const float*)d_in[6];
    const float* c    = (const float*)d_in[7];
    float* out = (float*)d_out;

    prep_kernel<<<(B_ * H_ * L_ * D_ / 4 + 255) / 256, 256>>>(
        (const float4*)ks, (const float4*)vs);
    lut_kernel<<<dim3((LUT_N + 128) / 128, H_), 128>>>(a, b, c);

    cudaFuncSetAttribute(attn_kernel,
                         cudaFuncAttributeMaxDynamicSharedMemorySize, SMEM_TOTAL);
    attn_kernel<<<dim3(L_ / 128, H_, B_), 256, SMEM_TOTAL>>>(qs, qs_s, ks_s, out);
}